// round 1
// baseline (speedup 1.0000x reference)
#include <cuda_runtime.h>
#include <math.h>

// Problem constants
#define BB 2
#define DD 128
#define HH 128
#define WW 128
#define NVOX (BB*DD*HH*WW)          // 4194304
#define PLANE (HH*WW)               // 16384

// ---------------- static device scratch (no runtime allocation) ----------------
__device__ float g_buf1[5u*NVOX];   // W-pass output, 5 channels
__device__ float g_buf2[5u*NVOX];   // H-pass output, 5 channels
__device__ float g_gm[2u*NVOX];     // gradient magnitude: pred, target
__device__ double g_part[3][64];    // partial sums: mse, ssim, gme
__device__ unsigned g_mm[4];        // minp, maxp, mint, maxt (float bits, all >0)

// ---------------- helpers ----------------
__device__ __forceinline__ int refl(int x) {      // jnp 'reflect' (no edge repeat)
    return x < 0 ? -x : (x > 127 ? 254 - x : x);
}

// Gaussian weights computed on device (exactly mirrors reference formula, fp32)
__device__ __forceinline__ void load_gauss(float* G) {
    if (threadIdx.x == 0 && threadIdx.y == 0) {
        float tmp[11]; float s = 0.f;
        #pragma unroll
        for (int i = 0; i < 11; i++) {
            float o = (float)(i - 5);
            tmp[i] = expf(-(o*o) / 4.5f);   // 2*1.5^2 = 4.5
            s += tmp[i];
        }
        #pragma unroll
        for (int i = 0; i < 11; i++) G[i] = tmp[i] / s;
    }
}

// Block-wide sum -> double partial slot (1D blocks, size multiple of 32, <=1024)
__device__ __forceinline__ void block_add(float v, int slot) {
    #pragma unroll
    for (int o = 16; o > 0; o >>= 1) v += __shfl_down_sync(0xffffffffu, v, o);
    __shared__ float red[32];
    int lane = threadIdx.x & 31, wid = threadIdx.x >> 5;
    if (lane == 0) red[wid] = v;
    __syncthreads();
    int nw = (blockDim.x + 31) >> 5;
    if (wid == 0) {
        float x = (lane < nw) ? red[lane] : 0.f;
        #pragma unroll
        for (int o = 16; o > 0; o >>= 1) x += __shfl_down_sync(0xffffffffu, x, o);
        if (lane == 0) atomicAdd(&g_part[slot][blockIdx.x & 63], (double)x);
    }
}

// ---------------- kernels ----------------
__global__ void init_kernel() {
    int t = threadIdx.x;
    if (t < 64) { g_part[0][t] = 0.0; g_part[1][t] = 0.0; g_part[2][t] = 0.0; }
    if (t == 0) {
        g_mm[0] = 0x7F800000u; g_mm[1] = 0u;   // pred  min=+inf, max=0
        g_mm[2] = 0x7F800000u; g_mm[3] = 0u;   // target
    }
}

// Pass 1: Gaussian along W of {p, t, p^2, t^2, p*t}; also MSE partials.
__global__ __launch_bounds__(WW) void pass_w(const float* __restrict__ p,
                                             const float* __restrict__ t) {
    __shared__ float sp[WW], st[WW], G[11];
    load_gauss(G);
    int row = blockIdx.x;                 // (b*DD + d)*HH + h
    size_t base = (size_t)row * WW;
    int w = threadIdx.x;
    float pv = p[base + w], tv = t[base + w];
    sp[w] = pv; st[w] = tv;
    __syncthreads();

    float a0=0.f, a1=0.f, a2=0.f, a3=0.f, a4=0.f;
    #pragma unroll
    for (int k = 0; k < 11; k++) {
        int ww = w + k - 5;
        if (ww >= 0 && ww < WW) {
            float g = G[k], x = sp[ww], y = st[ww];
            a0 += g * x; a1 += g * y;
            a2 += g * x * x; a3 += g * y * y; a4 += g * x * y;
        }
    }
    g_buf1[0u*NVOX + base + w] = a0;
    g_buf1[1u*NVOX + base + w] = a1;
    g_buf1[2u*NVOX + base + w] = a2;
    g_buf1[3u*NVOX + base + w] = a3;
    g_buf1[4u*NVOX + base + w] = a4;

    float d = pv - tv;
    block_add(d * d, 0);
}

// Pass 2: Gaussian along H (register ring buffer, one load per output).
// grid: (BB*DD, 5 channels, 2 h-chunks), block: WW
__global__ __launch_bounds__(WW) void pass_h() {
    __shared__ float G[11];
    load_gauss(G); __syncthreads();
    int bd = blockIdx.x, c = blockIdx.y, cz = blockIdx.z;
    int w = threadIdx.x;
    int h0 = cz * (HH/2);
    const float* src = g_buf1 + (size_t)c*NVOX + (size_t)bd*PLANE;
    float*       dst = g_buf2 + (size_t)c*NVOX + (size_t)bd*PLANE;

    float win[11];
    #pragma unroll
    for (int j = 0; j < 11; j++) {
        int hh = h0 + j - 5;
        win[j] = (hh >= 0 && hh < HH) ? src[hh*WW + w] : 0.f;
    }
    for (int h = h0; h < h0 + HH/2; h++) {
        float acc = 0.f;
        #pragma unroll
        for (int j = 0; j < 11; j++) acc += G[j] * win[j];
        dst[h*WW + w] = acc;
        #pragma unroll
        for (int j = 0; j < 10; j++) win[j] = win[j+1];
        int nh = h + 6;
        win[10] = (nh < HH) ? src[nh*WW + w] : 0.f;
    }
}

// Pass 3: Gaussian along D of all 5 channels + fused SSIM map + reduction.
// grid: (HH, BB, 2 d-chunks), block: WW
__global__ __launch_bounds__(WW) void pass_d_ssim() {
    __shared__ float G[11];
    load_gauss(G); __syncthreads();
    int h = blockIdx.x, b = blockIdx.y, cz = blockIdx.z;
    int w = threadIdx.x;
    int d0 = cz * (DD/2);
    size_t base0 = ((size_t)b*DD*HH + (size_t)h)*WW + w;   // + d*PLANE

    float win[5][11];
    #pragma unroll
    for (int c = 0; c < 5; c++)
        #pragma unroll
        for (int j = 0; j < 11; j++) {
            int d = d0 + j - 5;
            win[c][j] = (d >= 0 && d < DD)
                ? g_buf2[(size_t)c*NVOX + base0 + (size_t)d*PLANE] : 0.f;
        }

    float ssum = 0.f;
    for (int d = d0; d < d0 + DD/2; d++) {
        float f[5];
        #pragma unroll
        for (int c = 0; c < 5; c++) {
            float a = 0.f;
            #pragma unroll
            for (int j = 0; j < 11; j++) a += G[j] * win[c][j];
            f[c] = a;
        }
        float mu_p = f[0], mu_t = f[1];
        float mp2 = mu_p*mu_p, mt2 = mu_t*mu_t, mpt = mu_p*mu_t;
        float sp = f[2] - mp2, st = f[3] - mt2, spt = f[4] - mpt;
        float num = (2.f*mpt + 1e-4f) * (2.f*spt + 9e-4f);
        float den = (mp2 + mt2 + 1e-4f) * (sp + st + 9e-4f);
        ssum += num / den;

        int nd = d + 6;
        #pragma unroll
        for (int c = 0; c < 5; c++) {
            #pragma unroll
            for (int j = 0; j < 10; j++) win[c][j] = win[c][j+1];
            win[c][10] = (nd < DD)
                ? g_buf2[(size_t)c*NVOX + base0 + (size_t)nd*PLANE] : 0.f;
        }
    }
    block_add(ssum, 1);
}

// Sobel gradient magnitude for both volumes + global min/max.
// All 9 kernels factored into separable 1D combos of s=[1,2,1], c=[-1,0,1], o=[1,1,1]:
//   Sx=s(s)(c)  Sy=s(c)(s)  Sz=c(s)(s)
//   Sd11=B1-B2, Sd12=B1+B2  with B1=s,o,c  B2=s,c,o
//   Sd21=B3-B4, Sd22=B3+B4  with B3=c,o,s  B4=o,c,s
//   Sd31=B5-B6, Sd32=B5+B6  with B5=o,s,c  B6=c,s,o
// grid: (WW/32, HH/8, BB*DD), block: (32, 8)
__global__ __launch_bounds__(256) void sobel_kernel(const float* __restrict__ pred,
                                                    const float* __restrict__ targ) {
    __shared__ float tile[2][3][10][34];
    int tx = threadIdx.x, ty = threadIdx.y;
    int tid = ty * 32 + tx;
    int w0 = blockIdx.x * 32, h0 = blockIdx.y * 8;
    int bd = blockIdx.z;
    int b = bd >> 7, d = bd & 127;

    // cooperative halo load with reflect indexing
    for (int v = 0; v < 2; v++) {
        const float* src = v ? targ : pred;
        for (int idx = tid; idx < 3*10*34; idx += 256) {
            int i = idx / 340, rem = idx % 340;
            int r = rem / 34, cc = rem % 34;
            int gd = refl(d + i - 1), gh = refl(h0 + r - 1), gw = refl(w0 + cc - 1);
            tile[v][i][r][cc] = src[(((size_t)b*DD + gd)*HH + gh)*WW + gw];
        }
    }
    __syncthreads();

    float gmv[2];
    #pragma unroll
    for (int v = 0; v < 2; v++) {
        float P1[3],P2[3],P3[3],P4[3],P5[3],P6[3],P7[3];
        #pragma unroll
        for (int i = 0; i < 3; i++) {
            float ws[3], wc[3], wo[3];
            #pragma unroll
            for (int j = 0; j < 3; j++) {
                float x0 = tile[v][i][ty+j][tx];
                float x1 = tile[v][i][ty+j][tx+1];
                float x2 = tile[v][i][ty+j][tx+2];
                ws[j] = x0 + 2.f*x1 + x2;
                wc[j] = x2 - x0;
                wo[j] = x0 + x1 + x2;
            }
            P1[i] = wc[0] + 2.f*wc[1] + wc[2];   // s_j of c_k
            P2[i] = ws[2] - ws[0];               // c_j of s_k
            P3[i] = ws[0] + 2.f*ws[1] + ws[2];   // s_j of s_k
            P4[i] = wc[0] + wc[1] + wc[2];       // o_j of c_k
            P5[i] = wo[2] - wo[0];               // c_j of o_k
            P6[i] = ws[0] + ws[1] + ws[2];       // o_j of s_k
            P7[i] = wo[0] + 2.f*wo[1] + wo[2];   // s_j of o_k
        }
        float gx = P1[0] + 2.f*P1[1] + P1[2];    // Sx
        float gy = P2[0] + 2.f*P2[1] + P2[2];    // Sy
        float gz = P3[2] - P3[0];                // Sz
        float B1 = P4[0] + 2.f*P4[1] + P4[2];
        float B2 = P5[0] + 2.f*P5[1] + P5[2];
        float B3 = P6[2] - P6[0];
        float B4 = P2[0] + P2[1] + P2[2];
        float B5 = P1[0] + P1[1] + P1[2];
        float B6 = P7[2] - P7[0];
        float g3 = B1 - B2, g4 = B1 + B2;
        float g5 = B3 - B4, g6 = B3 + B4;
        float g7 = B5 - B6, g8 = B5 + B6;

        const float e = 1e-6f;
        float acc = 0.f;
        float q;
        q = gx + e; acc += q*q;  q = gy + e; acc += q*q;  q = gz + e; acc += q*q;
        q = g3 + e; acc += q*q;  q = g4 + e; acc += q*q;  q = g5 + e; acc += q*q;
        q = g6 + e; acc += q*q;  q = g7 + e; acc += q*q;  q = g8 + e; acc += q*q;
        gmv[v] = sqrtf(acc + 9e-6f);
    }

    size_t vox = (((size_t)b*DD + d)*HH + (h0 + ty))*WW + (w0 + tx);
    g_gm[vox]            = gmv[0];
    g_gm[(size_t)NVOX + vox] = gmv[1];

    // block min/max reduction (positive floats -> uint ordering)
    float mnp = gmv[0], mxp = gmv[0], mnt = gmv[1], mxt = gmv[1];
    #pragma unroll
    for (int o = 16; o > 0; o >>= 1) {
        mnp = fminf(mnp, __shfl_down_sync(0xffffffffu, mnp, o));
        mxp = fmaxf(mxp, __shfl_down_sync(0xffffffffu, mxp, o));
        mnt = fminf(mnt, __shfl_down_sync(0xffffffffu, mnt, o));
        mxt = fmaxf(mxt, __shfl_down_sync(0xffffffffu, mxt, o));
    }
    __shared__ float s4[4][8];
    int lane = tid & 31, wid = tid >> 5;
    if (lane == 0) { s4[0][wid]=mnp; s4[1][wid]=mxp; s4[2][wid]=mnt; s4[3][wid]=mxt; }
    __syncthreads();
    if (tid == 0) {
        float a = s4[0][0], bx = s4[1][0], cmin = s4[2][0], dmax = s4[3][0];
        #pragma unroll
        for (int i = 1; i < 8; i++) {
            a = fminf(a, s4[0][i]); bx = fmaxf(bx, s4[1][i]);
            cmin = fminf(cmin, s4[2][i]); dmax = fmaxf(dmax, s4[3][i]);
        }
        atomicMin(&g_mm[0], __float_as_uint(a));
        atomicMax(&g_mm[1], __float_as_uint(bx));
        atomicMin(&g_mm[2], __float_as_uint(cmin));
        atomicMax(&g_mm[3], __float_as_uint(dmax));
    }
}

// GME: mean |norm(gm_p) - norm(gm_t)|
__global__ __launch_bounds__(256) void gme_kernel() {
    float minp = __uint_as_float(g_mm[0]), maxp = __uint_as_float(g_mm[1]);
    float mint = __uint_as_float(g_mm[2]), maxt = __uint_as_float(g_mm[3]);
    float ip = 1.f / (maxp - minp + 1e-6f);
    float it = 1.f / (maxt - mint + 1e-6f);
    float acc = 0.f;
    for (size_t i = (size_t)blockIdx.x*blockDim.x + threadIdx.x; i < NVOX;
         i += (size_t)gridDim.x*blockDim.x) {
        float np = (g_gm[i] - minp) * ip;
        float nt = (g_gm[(size_t)NVOX + i] - mint) * it;
        acc += fabsf(np - nt);
    }
    block_add(acc, 2);
}

__global__ void finalize_kernel(float* out, int out_size) {
    if (threadIdx.x == 0) {
        double s0 = 0.0, s1 = 0.0, s2 = 0.0;
        for (int i = 0; i < 64; i++) { s0 += g_part[0][i]; s1 += g_part[1][i]; s2 += g_part[2][i]; }
        const double inv = 1.0 / (double)NVOX;
        double mse  = s0 * inv;
        double ssim = 1.0 - s1 * inv;
        double gme  = 1e-6 + s2 * inv;
        double total = mse + ssim + 0.7 * gme;
        if (out_size > 0) out[0] = (float)total;
        if (out_size > 1) out[1] = (float)mse;
        if (out_size > 2) out[2] = (float)ssim;
        if (out_size > 3) out[3] = (float)gme;
    }
}

// ---------------- launch ----------------
extern "C" void kernel_launch(void* const* d_in, const int* in_sizes, int n_in,
                              void* d_out, int out_size) {
    const float* pred = (const float*)d_in[0];
    const float* targ = (const float*)d_in[1];
    float* out = (float*)d_out;

    init_kernel<<<1, 64>>>();
    pass_w<<<BB*DD*HH, WW>>>(pred, targ);
    pass_h<<<dim3(BB*DD, 5, 2), WW>>>();
    pass_d_ssim<<<dim3(HH, BB, 2), WW>>>();
    sobel_kernel<<<dim3(WW/32, HH/8, BB*DD), dim3(32, 8)>>>(pred, targ);
    gme_kernel<<<2048, 256>>>();
    finalize_kernel<<<1, 32>>>(out, out_size);
}

// round 2
// speedup vs baseline: 1.2796x; 1.2796x over previous
#include <cuda_runtime.h>
#include <math.h>

// Problem constants
#define BB 2
#define DD 128
#define HH 128
#define WW 128
#define NVOX (BB*DD*HH*WW)          // 4194304
#define PLANE (HH*WW)               // 16384

// ---------------- static device scratch (no runtime allocation) ----------------
__device__ float g_buf2[5u*NVOX];   // W+H filtered, 5 channels
__device__ float g_gm[2u*NVOX];     // gradient magnitude: pred, target
__device__ double g_part[3][64];    // partial sums: mse, ssim, gme
__device__ unsigned g_mm[4];        // minp, maxp, mint, maxt (float bits, all >0)

// ---------------- helpers ----------------
__device__ __forceinline__ int refl(int x) {      // jnp 'reflect' (no edge repeat)
    return x < 0 ? -x : (x > 127 ? 254 - x : x);
}

// Gaussian weights computed on device (exactly mirrors reference formula, fp32)
__device__ __forceinline__ void load_gauss(float* G) {
    if (threadIdx.x == 0 && threadIdx.y == 0) {
        float tmp[11]; float s = 0.f;
        #pragma unroll
        for (int i = 0; i < 11; i++) {
            float o = (float)(i - 5);
            tmp[i] = expf(-(o*o) / 4.5f);   // 2*1.5^2 = 4.5
            s += tmp[i];
        }
        #pragma unroll
        for (int i = 0; i < 11; i++) G[i] = tmp[i] / s;
    }
}

// Block-wide sum -> double partial slot (1D blocks, size multiple of 32, <=1024)
__device__ __forceinline__ void block_add(float v, int slot) {
    #pragma unroll
    for (int o = 16; o > 0; o >>= 1) v += __shfl_down_sync(0xffffffffu, v, o);
    __shared__ float red[32];
    int lane = threadIdx.x & 31, wid = threadIdx.x >> 5;
    if (lane == 0) red[wid] = v;
    __syncthreads();
    int nw = (blockDim.x + 31) >> 5;
    if (wid == 0) {
        float x = (lane < nw) ? red[lane] : 0.f;
        #pragma unroll
        for (int o = 16; o > 0; o >>= 1) x += __shfl_down_sync(0xffffffffu, x, o);
        if (lane == 0) atomicAdd(&g_part[slot][blockIdx.x & 63], (double)x);
    }
}

// ---------------- kernels ----------------
__global__ void init_kernel() {
    int t = threadIdx.x;
    if (t < 64) { g_part[0][t] = 0.0; g_part[1][t] = 0.0; g_part[2][t] = 0.0; }
    if (t == 0) {
        g_mm[0] = 0x7F800000u; g_mm[1] = 0u;   // pred  min=+inf, max=0
        g_mm[2] = 0x7F800000u; g_mm[3] = 0u;   // target
    }
}

// Fused W+H Gaussian of {p, t, p^2, t^2, p*t} + MSE partials.
// grid: (BB*DD, 4 h-chunks), block: 128 (w). Ring buffer along H in registers,
// W-conv via double-buffered smem rows of the 5 products.
#define HCH 4
#define HROWS (HH/HCH)   // 32
__global__ __launch_bounds__(128) void fused_wh(const float* __restrict__ p,
                                                const float* __restrict__ t) {
    __shared__ float G[11];
    __shared__ float q[2][5][WW];
    load_gauss(G);
    int bd = blockIdx.x;
    int h0 = blockIdx.y * HROWS;
    int w  = threadIdx.x;
    size_t sbase = (size_t)bd * PLANE;

    float win[5][11];
    float msea = 0.f;

    // helper macro: load row hh of p,t, compute products into q[par], then W-filter.
    // One __syncthreads per row (double buffered).
    #define PROCESS_ROW(hh, par, DEST0,DEST1,DEST2,DEST3,DEST4)                         \
    {                                                                                   \
        int _hh = (hh); int _ok = (_hh >= 0 && _hh < HH);                               \
        if (_ok) {                                                                      \
            float pv = p[sbase + (size_t)_hh*WW + w];                                   \
            float tv = t[sbase + (size_t)_hh*WW + w];                                   \
            q[par][0][w] = pv; q[par][1][w] = tv;                                       \
            q[par][2][w] = pv*pv; q[par][3][w] = tv*tv; q[par][4][w] = pv*tv;           \
            if (_hh >= h0 && _hh < h0 + HROWS) { float dv = pv - tv; msea += dv*dv; }   \
        }                                                                               \
        __syncthreads();                                                                \
        float a0=0.f,a1=0.f,a2=0.f,a3=0.f,a4=0.f;                                       \
        if (_ok) {                                                                      \
            _Pragma("unroll")                                                           \
            for (int k = 0; k < 11; k++) {                                              \
                int ww = w + k - 5;                                                     \
                if (ww >= 0 && ww < WW) {                                               \
                    float g = G[k];                                                     \
                    a0 += g * q[par][0][ww];                                            \
                    a1 += g * q[par][1][ww];                                            \
                    a2 += g * q[par][2][ww];                                            \
                    a3 += g * q[par][3][ww];                                            \
                    a4 += g * q[par][4][ww];                                            \
                }                                                                       \
            }                                                                           \
        }                                                                               \
        DEST0 = a0; DEST1 = a1; DEST2 = a2; DEST3 = a3; DEST4 = a4;                     \
    }

    // preload 11-row window: rows h0-5 .. h0+5
    #pragma unroll
    for (int j = 0; j < 11; j++) {
        PROCESS_ROW(h0 + j - 5, (j & 1),
                    win[0][j], win[1][j], win[2][j], win[3][j], win[4][j]);
    }

    int par = 11 & 1;  // parity of the next row index
    for (int h = h0; h < h0 + HROWS; h++) {
        // H-conv output at row h
        #pragma unroll
        for (int c = 0; c < 5; c++) {
            float acc = 0.f;
            #pragma unroll
            for (int j = 0; j < 11; j++) acc += G[j] * win[c][j];
            g_buf2[(size_t)c*NVOX + sbase + (size_t)h*WW + w] = acc;
        }
        // shift window, bring in row h+6
        float n0,n1,n2,n3,n4;
        PROCESS_ROW(h + 6, par, n0,n1,n2,n3,n4);
        par ^= 1;
        #pragma unroll
        for (int j = 0; j < 10; j++) {
            win[0][j]=win[0][j+1]; win[1][j]=win[1][j+1]; win[2][j]=win[2][j+1];
            win[3][j]=win[3][j+1]; win[4][j]=win[4][j+1];
        }
        win[0][10]=n0; win[1][10]=n1; win[2][10]=n2; win[3][10]=n3; win[4][10]=n4;
    }
    #undef PROCESS_ROW

    block_add(msea, 0);
}

// Gaussian along D of all 5 channels + fused SSIM map + reduction.
// grid: (HH, BB, DCH d-chunks), block: WW
#define DCH 4
#define DROWS (DD/DCH)  // 32
__global__ __launch_bounds__(WW) void pass_d_ssim() {
    __shared__ float G[11];
    load_gauss(G); __syncthreads();
    int h = blockIdx.x, b = blockIdx.y, cz = blockIdx.z;
    int w = threadIdx.x;
    int d0 = cz * DROWS;
    size_t base0 = ((size_t)b*DD*HH + (size_t)h)*WW + w;   // + d*PLANE
    const float* __restrict__ src = g_buf2;

    float win[5][11];
    #pragma unroll
    for (int c = 0; c < 5; c++)
        #pragma unroll
        for (int j = 0; j < 11; j++) {
            int d = d0 + j - 5;
            win[c][j] = (d >= 0 && d < DD)
                ? src[(size_t)c*NVOX + base0 + (size_t)d*PLANE] : 0.f;
        }

    float ssum = 0.f;
    for (int d = d0; d < d0 + DROWS; d++) {
        float f[5];
        #pragma unroll
        for (int c = 0; c < 5; c++) {
            float a = 0.f;
            #pragma unroll
            for (int j = 0; j < 11; j++) a += G[j] * win[c][j];
            f[c] = a;
        }
        float mu_p = f[0], mu_t = f[1];
        float mp2 = mu_p*mu_p, mt2 = mu_t*mu_t, mpt = mu_p*mu_t;
        float sp = f[2] - mp2, st = f[3] - mt2, spt = f[4] - mpt;
        float num = (2.f*mpt + 1e-4f) * (2.f*spt + 9e-4f);
        float den = (mp2 + mt2 + 1e-4f) * (sp + st + 9e-4f);
        ssum += num / den;

        int nd = d + 6;
        #pragma unroll
        for (int c = 0; c < 5; c++) {
            #pragma unroll
            for (int j = 0; j < 10; j++) win[c][j] = win[c][j+1];
            win[c][10] = (nd < DD)
                ? src[(size_t)c*NVOX + base0 + (size_t)nd*PLANE] : 0.f;
        }
    }
    block_add(ssum, 1);
}

// Sobel gradient magnitude, sliding along D with rotating per-plane partials.
// Per plane, per thread compute 7 separable partials (P1..P7) reused by 3 outputs.
//   Sx=s(s)(c)  Sy=s(c)(s)  Sz=c(s)(s)
//   Sd11=B1-B2, Sd12=B1+B2; Sd21=B3-B4, Sd22=B3+B4; Sd31=B5-B6, Sd32=B5+B6
// grid: (WW/32, HH/8, BB*16), block: (32,8). Each block: 8 output planes.
__global__ __launch_bounds__(256) void sobel_kernel(const float* __restrict__ pred,
                                                    const float* __restrict__ targ) {
    __shared__ float tile[2][10][34];
    int tx = threadIdx.x, ty = threadIdx.y;
    int tid = ty * 32 + tx;
    int w0 = blockIdx.x * 32, h0 = blockIdx.y * 8;
    int z = blockIdx.z;
    int b = z >> 4, d0 = (z & 15) * 8;

    float P[2][3][7];
    float mn0 = 3.4e38f, mx0 = 0.f, mn1 = 3.4e38f, mx1 = 0.f;

    #pragma unroll 1
    for (int i = 0; i < 10; i++) {
        int gd = refl(d0 - 1 + i);
        // cooperative halo load of plane gd, both volumes
        for (int idx = tid; idx < 2*10*34; idx += 256) {
            int v = idx / 340, rem = idx % 340;
            int r = rem / 34, cc = rem % 34;
            int gh = refl(h0 + r - 1), gw = refl(w0 + cc - 1);
            tile[v][r][cc] = (v ? targ : pred)[((size_t)b*DD + gd)*PLANE + (size_t)gh*WW + gw];
        }
        __syncthreads();

        int ri = i % 3;
        #pragma unroll
        for (int v = 0; v < 2; v++) {
            float ws[3], wc[3], wo[3];
            #pragma unroll
            for (int j = 0; j < 3; j++) {
                float x0 = tile[v][ty+j][tx];
                float x1 = tile[v][ty+j][tx+1];
                float x2 = tile[v][ty+j][tx+2];
                ws[j] = x0 + 2.f*x1 + x2;
                wc[j] = x2 - x0;
                wo[j] = x0 + x1 + x2;
            }
            P[v][ri][0] = wc[0] + 2.f*wc[1] + wc[2];   // s_h of c_w
            P[v][ri][1] = ws[2] - ws[0];               // c_h of s_w
            P[v][ri][2] = ws[0] + 2.f*ws[1] + ws[2];   // s_h of s_w
            P[v][ri][3] = wc[0] + wc[1] + wc[2];       // o_h of c_w
            P[v][ri][4] = wo[2] - wo[0];               // c_h of o_w
            P[v][ri][5] = ws[0] + ws[1] + ws[2];       // o_h of s_w
            P[v][ri][6] = wo[0] + 2.f*wo[1] + wo[2];   // s_h of o_w
        }
        __syncthreads();   // WAR: tile reuse next iteration

        if (i >= 2) {
            int dm = (i - 2) % 3, dc = (i - 1) % 3, dp = ri;
            int d = d0 + i - 2;
            float gmv[2];
            #pragma unroll
            for (int v = 0; v < 2; v++) {
                float gx = P[v][dm][0] + 2.f*P[v][dc][0] + P[v][dp][0];   // Sx
                float gy = P[v][dm][1] + 2.f*P[v][dc][1] + P[v][dp][1];   // Sy
                float gz = P[v][dp][2] - P[v][dm][2];                     // Sz
                float B1 = P[v][dm][3] + 2.f*P[v][dc][3] + P[v][dp][3];
                float B2 = P[v][dm][4] + 2.f*P[v][dc][4] + P[v][dp][4];
                float B3 = P[v][dp][5] - P[v][dm][5];
                float B4 = P[v][dm][1] + P[v][dc][1] + P[v][dp][1];
                float B5 = P[v][dm][0] + P[v][dc][0] + P[v][dp][0];
                float B6 = P[v][dp][6] - P[v][dm][6];
                float g3 = B1 - B2, g4 = B1 + B2;
                float g5 = B3 - B4, g6 = B3 + B4;
                float g7 = B5 - B6, g8 = B5 + B6;

                const float e = 1e-6f;
                float acc = 0.f, qv;
                qv = gx + e; acc += qv*qv;  qv = gy + e; acc += qv*qv;
                qv = gz + e; acc += qv*qv;  qv = g3 + e; acc += qv*qv;
                qv = g4 + e; acc += qv*qv;  qv = g5 + e; acc += qv*qv;
                qv = g6 + e; acc += qv*qv;  qv = g7 + e; acc += qv*qv;
                qv = g8 + e; acc += qv*qv;
                gmv[v] = sqrtf(acc + 9e-6f);
            }
            size_t vox = (((size_t)b*DD + d)*HH + (h0 + ty))*WW + (w0 + tx);
            g_gm[vox]                = gmv[0];
            g_gm[(size_t)NVOX + vox] = gmv[1];
            mn0 = fminf(mn0, gmv[0]); mx0 = fmaxf(mx0, gmv[0]);
            mn1 = fminf(mn1, gmv[1]); mx1 = fmaxf(mx1, gmv[1]);
        }
    }

    // block min/max reduction (positive floats -> uint ordering)
    #pragma unroll
    for (int o = 16; o > 0; o >>= 1) {
        mn0 = fminf(mn0, __shfl_down_sync(0xffffffffu, mn0, o));
        mx0 = fmaxf(mx0, __shfl_down_sync(0xffffffffu, mx0, o));
        mn1 = fminf(mn1, __shfl_down_sync(0xffffffffu, mn1, o));
        mx1 = fmaxf(mx1, __shfl_down_sync(0xffffffffu, mx1, o));
    }
    __shared__ float s4[4][8];
    int lane = tid & 31, wid = tid >> 5;
    if (lane == 0) { s4[0][wid]=mn0; s4[1][wid]=mx0; s4[2][wid]=mn1; s4[3][wid]=mx1; }
    __syncthreads();
    if (tid == 0) {
        float a = s4[0][0], bx = s4[1][0], cmin = s4[2][0], dmax = s4[3][0];
        #pragma unroll
        for (int i = 1; i < 8; i++) {
            a = fminf(a, s4[0][i]); bx = fmaxf(bx, s4[1][i]);
            cmin = fminf(cmin, s4[2][i]); dmax = fmaxf(dmax, s4[3][i]);
        }
        atomicMin(&g_mm[0], __float_as_uint(a));
        atomicMax(&g_mm[1], __float_as_uint(bx));
        atomicMin(&g_mm[2], __float_as_uint(cmin));
        atomicMax(&g_mm[3], __float_as_uint(dmax));
    }
}

// GME: mean |norm(gm_p) - norm(gm_t)|
__global__ __launch_bounds__(256) void gme_kernel() {
    const float* __restrict__ gm = g_gm;
    float minp = __uint_as_float(g_mm[0]), maxp = __uint_as_float(g_mm[1]);
    float mint = __uint_as_float(g_mm[2]), maxt = __uint_as_float(g_mm[3]);
    float ip = 1.f / (maxp - minp + 1e-6f);
    float it = 1.f / (maxt - mint + 1e-6f);
    float acc = 0.f;
    for (size_t i = (size_t)blockIdx.x*blockDim.x + threadIdx.x; i < NVOX;
         i += (size_t)gridDim.x*blockDim.x) {
        float np = (gm[i] - minp) * ip;
        float nt = (gm[(size_t)NVOX + i] - mint) * it;
        acc += fabsf(np - nt);
    }
    block_add(acc, 2);
}

__global__ void finalize_kernel(float* out, int out_size) {
    if (threadIdx.x == 0) {
        double s0 = 0.0, s1 = 0.0, s2 = 0.0;
        for (int i = 0; i < 64; i++) { s0 += g_part[0][i]; s1 += g_part[1][i]; s2 += g_part[2][i]; }
        const double inv = 1.0 / (double)NVOX;
        double mse  = s0 * inv;
        double ssim = 1.0 - s1 * inv;
        double gme  = 1e-6 + s2 * inv;
        double total = mse + ssim + 0.7 * gme;
        if (out_size > 0) out[0] = (float)total;
        if (out_size > 1) out[1] = (float)mse;
        if (out_size > 2) out[2] = (float)ssim;
        if (out_size > 3) out[3] = (float)gme;
    }
}

// ---------------- launch ----------------
extern "C" void kernel_launch(void* const* d_in, const int* in_sizes, int n_in,
                              void* d_out, int out_size) {
    const float* pred = (const float*)d_in[0];
    const float* targ = (const float*)d_in[1];
    float* out = (float*)d_out;

    init_kernel<<<1, 64>>>();
    fused_wh<<<dim3(BB*DD, HCH), 128>>>(pred, targ);
    pass_d_ssim<<<dim3(HH, BB, DCH), WW>>>();
    sobel_kernel<<<dim3(WW/32, HH/8, BB*16), dim3(32, 8)>>>(pred, targ);
    gme_kernel<<<2048, 256>>>();
    finalize_kernel<<<1, 32>>>(out, out_size);
}

// round 3
// speedup vs baseline: 1.3545x; 1.0585x over previous
#include <cuda_runtime.h>
#include <math.h>

// Problem constants
#define BB 2
#define DD 128
#define HH 128
#define WW 128
#define NVOX (BB*DD*HH*WW)          // 4194304
#define PLANE (HH*WW)               // 16384

// ---------------- static device scratch (no runtime allocation) ----------------
__device__ float g_buf2[5u*NVOX];   // W+H filtered, 5 channels
__device__ float g_gm[2u*NVOX];     // gradient magnitude: pred, target
__device__ double g_part[3][64];    // partial sums: mse, ssim, gme
__device__ unsigned g_mm[4];        // minp, maxp, mint, maxt (float bits, all >0)

// ---------------- helpers ----------------
__device__ __forceinline__ int refl(int x) {      // jnp 'reflect' (no edge repeat)
    return x < 0 ? -x : (x > 127 ? 254 - x : x);
}

// Gaussian weights computed on device (exactly mirrors reference formula, fp32)
__device__ __forceinline__ void load_gauss(float* G) {
    if (threadIdx.x == 0 && threadIdx.y == 0) {
        float tmp[11]; float s = 0.f;
        #pragma unroll
        for (int i = 0; i < 11; i++) {
            float o = (float)(i - 5);
            tmp[i] = expf(-(o*o) / 4.5f);   // 2*1.5^2 = 4.5
            s += tmp[i];
        }
        #pragma unroll
        for (int i = 0; i < 11; i++) G[i] = tmp[i] / s;
    }
}

// Block-wide sum -> double partial slot (1D blocks, size multiple of 32, <=1024)
__device__ __forceinline__ void block_add(float v, int slot) {
    #pragma unroll
    for (int o = 16; o > 0; o >>= 1) v += __shfl_down_sync(0xffffffffu, v, o);
    __shared__ float red[32];
    int lane = threadIdx.x & 31, wid = threadIdx.x >> 5;
    if (lane == 0) red[wid] = v;
    __syncthreads();
    int nw = (blockDim.x + 31) >> 5;
    if (wid == 0) {
        float x = (lane < nw) ? red[lane] : 0.f;
        #pragma unroll
        for (int o = 16; o > 0; o >>= 1) x += __shfl_down_sync(0xffffffffu, x, o);
        if (lane == 0) atomicAdd(&g_part[slot][blockIdx.x & 63], (double)x);
    }
}

// ---------------- kernels ----------------
__global__ void init_kernel() {
    int t = threadIdx.x;
    if (t < 64) { g_part[0][t] = 0.0; g_part[1][t] = 0.0; g_part[2][t] = 0.0; }
    if (t == 0) {
        g_mm[0] = 0x7F800000u; g_mm[1] = 0u;   // pred  min=+inf, max=0
        g_mm[2] = 0x7F800000u; g_mm[3] = 0u;   // target
    }
}

// Fused W+H Gaussian of {p, t, p^2, t^2, p*t} + MSE partials.
// grid: (BB*DD, 4 h-chunks), block: 128 (w). Ring buffer along H in registers,
// W-conv via double-buffered smem rows of the 5 products.
#define HCH 4
#define HROWS (HH/HCH)   // 32
__global__ __launch_bounds__(128) void fused_wh(const float* __restrict__ p,
                                                const float* __restrict__ t) {
    __shared__ float G[11];
    __shared__ float q[2][5][WW];
    load_gauss(G);
    int bd = blockIdx.x;
    int h0 = blockIdx.y * HROWS;
    int w  = threadIdx.x;
    size_t sbase = (size_t)bd * PLANE;

    float win[5][11];
    float msea = 0.f;

    #define PROCESS_ROW(hh, par, DEST0,DEST1,DEST2,DEST3,DEST4)                         \
    {                                                                                   \
        int _hh = (hh); int _ok = (_hh >= 0 && _hh < HH);                               \
        if (_ok) {                                                                      \
            float pv = p[sbase + (size_t)_hh*WW + w];                                   \
            float tv = t[sbase + (size_t)_hh*WW + w];                                   \
            q[par][0][w] = pv; q[par][1][w] = tv;                                       \
            q[par][2][w] = pv*pv; q[par][3][w] = tv*tv; q[par][4][w] = pv*tv;           \
            if (_hh >= h0 && _hh < h0 + HROWS) { float dv = pv - tv; msea += dv*dv; }   \
        }                                                                               \
        __syncthreads();                                                                \
        float a0=0.f,a1=0.f,a2=0.f,a3=0.f,a4=0.f;                                       \
        if (_ok) {                                                                      \
            _Pragma("unroll")                                                           \
            for (int k = 0; k < 11; k++) {                                              \
                int ww = w + k - 5;                                                     \
                if (ww >= 0 && ww < WW) {                                               \
                    float g = G[k];                                                     \
                    a0 += g * q[par][0][ww];                                            \
                    a1 += g * q[par][1][ww];                                            \
                    a2 += g * q[par][2][ww];                                            \
                    a3 += g * q[par][3][ww];                                            \
                    a4 += g * q[par][4][ww];                                            \
                }                                                                       \
            }                                                                           \
        }                                                                               \
        DEST0 = a0; DEST1 = a1; DEST2 = a2; DEST3 = a3; DEST4 = a4;                     \
    }

    #pragma unroll
    for (int j = 0; j < 11; j++) {
        PROCESS_ROW(h0 + j - 5, (j & 1),
                    win[0][j], win[1][j], win[2][j], win[3][j], win[4][j]);
    }

    int par = 11 & 1;
    for (int h = h0; h < h0 + HROWS; h++) {
        #pragma unroll
        for (int c = 0; c < 5; c++) {
            float acc = 0.f;
            #pragma unroll
            for (int j = 0; j < 11; j++) acc += G[j] * win[c][j];
            g_buf2[(size_t)c*NVOX + sbase + (size_t)h*WW + w] = acc;
        }
        float n0,n1,n2,n3,n4;
        PROCESS_ROW(h + 6, par, n0,n1,n2,n3,n4);
        par ^= 1;
        #pragma unroll
        for (int j = 0; j < 10; j++) {
            win[0][j]=win[0][j+1]; win[1][j]=win[1][j+1]; win[2][j]=win[2][j+1];
            win[3][j]=win[3][j+1]; win[4][j]=win[4][j+1];
        }
        win[0][10]=n0; win[1][10]=n1; win[2][10]=n2; win[3][10]=n3; win[4][10]=n4;
    }
    #undef PROCESS_ROW

    block_add(msea, 0);
}

// Gaussian along D of all 5 channels + fused SSIM map + reduction.
// grid: (HH, BB, DCH d-chunks), block: WW
#define DCH 8
#define DROWS (DD/DCH)  // 16
__global__ __launch_bounds__(WW) void pass_d_ssim() {
    __shared__ float G[11];
    load_gauss(G); __syncthreads();
    int h = blockIdx.x, b = blockIdx.y, cz = blockIdx.z;
    int w = threadIdx.x;
    int d0 = cz * DROWS;
    size_t base0 = ((size_t)b*DD*HH + (size_t)h)*WW + w;   // + d*PLANE
    const float* __restrict__ src = g_buf2;

    float win[5][11];
    #pragma unroll
    for (int c = 0; c < 5; c++)
        #pragma unroll
        for (int j = 0; j < 11; j++) {
            int d = d0 + j - 5;
            win[c][j] = (d >= 0 && d < DD)
                ? src[(size_t)c*NVOX + base0 + (size_t)d*PLANE] : 0.f;
        }

    float ssum = 0.f;
    for (int d = d0; d < d0 + DROWS; d++) {
        float f[5];
        #pragma unroll
        for (int c = 0; c < 5; c++) {
            float a = 0.f;
            #pragma unroll
            for (int j = 0; j < 11; j++) a += G[j] * win[c][j];
            f[c] = a;
        }
        float mu_p = f[0], mu_t = f[1];
        float mp2 = mu_p*mu_p, mt2 = mu_t*mu_t, mpt = mu_p*mu_t;
        float sp = f[2] - mp2, st = f[3] - mt2, spt = f[4] - mpt;
        float num = (2.f*mpt + 1e-4f) * (2.f*spt + 9e-4f);
        float den = (mp2 + mt2 + 1e-4f) * (sp + st + 9e-4f);
        ssum += num / den;

        int nd = d + 6;
        #pragma unroll
        for (int c = 0; c < 5; c++) {
            #pragma unroll
            for (int j = 0; j < 10; j++) win[c][j] = win[c][j+1];
            win[c][10] = (nd < DD)
                ? src[(size_t)c*NVOX + base0 + (size_t)nd*PLANE] : 0.f;
        }
    }
    block_add(ssum, 1);
}

// Structured halo load of one (b, gd) plane into buf[2][10][36] (pred,targ).
// ty owns rows {ty, ty+8 (ty<2)}, tx owns interior col tx+1; lanes 0/31 load W-halo.
__device__ __forceinline__ void load_plane(float buf[2][10][36],
                                           const float* __restrict__ pred,
                                           const float* __restrict__ targ,
                                           int b, int gd, int h0, int w0,
                                           int tx, int ty) {
    size_t pbase = ((size_t)b*DD + gd)*PLANE;
    #pragma unroll
    for (int rr = 0; rr < 2; rr++) {
        int r = ty + rr*8;
        if (rr == 0 || ty < 2) {
            int gh = refl(h0 + r - 1);
            size_t rbase = pbase + (size_t)gh*WW;
            int gw = w0 + tx;
            buf[0][r][tx+1] = pred[rbase + gw];
            buf[1][r][tx+1] = targ[rbase + gw];
            if (tx == 0) {
                int gl = refl(w0 - 1);
                buf[0][r][0] = pred[rbase + gl];
                buf[1][r][0] = targ[rbase + gl];
            } else if (tx == 31) {
                int gr = refl(w0 + 32);
                buf[0][r][33] = pred[rbase + gr];
                buf[1][r][33] = targ[rbase + gr];
            }
        }
    }
}

// Sobel gradient magnitude, sliding along D (fully unrolled, register partials).
//   Sx=s(s)(c)  Sy=s(c)(s)  Sz=c(s)(s)
//   Sd11=B1-B2, Sd12=B1+B2; Sd21=B3-B4, Sd22=B3+B4; Sd31=B5-B6, Sd32=B5+B6
// grid: (WW/32, HH/8, BB*16), block: (32,8). Each block: 8 output planes.
__global__ __launch_bounds__(256) void sobel_kernel(const float* __restrict__ pred,
                                                    const float* __restrict__ targ) {
    __shared__ float tile[2][2][10][36];   // [parity][vol][row][col]
    int tx = threadIdx.x, ty = threadIdx.y;
    int tid = ty * 32 + tx;
    int w0 = blockIdx.x * 32, h0 = blockIdx.y * 8;
    int z = blockIdx.z;
    int b = z >> 4, d0 = (z & 15) * 8;

    float P[2][3][7];
    float mn0 = 3.4e38f, mx0 = 0.f, mn1 = 3.4e38f, mx1 = 0.f;

    load_plane(tile[0], pred, targ, b, refl(d0 - 1), h0, w0, tx, ty);

    #pragma unroll
    for (int i = 0; i < 10; i++) {
        __syncthreads();                         // tile[i&1] ready
        if (i < 9)
            load_plane(tile[(i+1)&1], pred, targ, b, refl(d0 + i), h0, w0, tx, ty);

        const int ri = i % 3;
        #pragma unroll
        for (int v = 0; v < 2; v++) {
            float ws[3], wc[3], wo[3];
            #pragma unroll
            for (int j = 0; j < 3; j++) {
                float x0 = tile[i&1][v][ty+j][tx];
                float x1 = tile[i&1][v][ty+j][tx+1];
                float x2 = tile[i&1][v][ty+j][tx+2];
                ws[j] = x0 + 2.f*x1 + x2;
                wc[j] = x2 - x0;
                wo[j] = x0 + x1 + x2;
            }
            P[v][ri][0] = wc[0] + 2.f*wc[1] + wc[2];   // s_h of c_w
            P[v][ri][1] = ws[2] - ws[0];               // c_h of s_w
            P[v][ri][2] = ws[0] + 2.f*ws[1] + ws[2];   // s_h of s_w
            P[v][ri][3] = wc[0] + wc[1] + wc[2];       // o_h of c_w
            P[v][ri][4] = wo[2] - wo[0];               // c_h of o_w
            P[v][ri][5] = ws[0] + ws[1] + ws[2];       // o_h of s_w
            P[v][ri][6] = wo[0] + 2.f*wo[1] + wo[2];   // s_h of o_w
        }

        if (i >= 2) {
            const int dm = (i - 2) % 3, dc = (i - 1) % 3, dp = ri;
            int d = d0 + i - 2;
            float gmv[2];
            #pragma unroll
            for (int v = 0; v < 2; v++) {
                float gx = P[v][dm][0] + 2.f*P[v][dc][0] + P[v][dp][0];   // Sx
                float gy = P[v][dm][1] + 2.f*P[v][dc][1] + P[v][dp][1];   // Sy
                float gz = P[v][dp][2] - P[v][dm][2];                     // Sz
                float B1 = P[v][dm][3] + 2.f*P[v][dc][3] + P[v][dp][3];
                float B2 = P[v][dm][4] + 2.f*P[v][dc][4] + P[v][dp][4];
                float B3 = P[v][dp][5] - P[v][dm][5];
                float B4 = P[v][dm][1] + P[v][dc][1] + P[v][dp][1];
                float B5 = P[v][dm][0] + P[v][dc][0] + P[v][dp][0];
                float B6 = P[v][dp][6] - P[v][dm][6];
                float g3 = B1 - B2, g4 = B1 + B2;
                float g5 = B3 - B4, g6 = B3 + B4;
                float g7 = B5 - B6, g8 = B5 + B6;

                const float e = 1e-6f;
                float acc = 0.f, qv;
                qv = gx + e; acc += qv*qv;  qv = gy + e; acc += qv*qv;
                qv = gz + e; acc += qv*qv;  qv = g3 + e; acc += qv*qv;
                qv = g4 + e; acc += qv*qv;  qv = g5 + e; acc += qv*qv;
                qv = g6 + e; acc += qv*qv;  qv = g7 + e; acc += qv*qv;
                qv = g8 + e; acc += qv*qv;
                gmv[v] = sqrtf(acc + 9e-6f);
            }
            size_t vox = (((size_t)b*DD + d)*HH + (h0 + ty))*WW + (w0 + tx);
            g_gm[vox]                = gmv[0];
            g_gm[(size_t)NVOX + vox] = gmv[1];
            mn0 = fminf(mn0, gmv[0]); mx0 = fmaxf(mx0, gmv[0]);
            mn1 = fminf(mn1, gmv[1]); mx1 = fmaxf(mx1, gmv[1]);
        }
    }

    // block min/max reduction (positive floats -> uint ordering)
    #pragma unroll
    for (int o = 16; o > 0; o >>= 1) {
        mn0 = fminf(mn0, __shfl_down_sync(0xffffffffu, mn0, o));
        mx0 = fmaxf(mx0, __shfl_down_sync(0xffffffffu, mx0, o));
        mn1 = fminf(mn1, __shfl_down_sync(0xffffffffu, mn1, o));
        mx1 = fmaxf(mx1, __shfl_down_sync(0xffffffffu, mx1, o));
    }
    __shared__ float s4[4][8];
    int lane = tid & 31, wid = tid >> 5;
    if (lane == 0) { s4[0][wid]=mn0; s4[1][wid]=mx0; s4[2][wid]=mn1; s4[3][wid]=mx1; }
    __syncthreads();
    if (tid == 0) {
        float a = s4[0][0], bx = s4[1][0], cmin = s4[2][0], dmax = s4[3][0];
        #pragma unroll
        for (int i = 1; i < 8; i++) {
            a = fminf(a, s4[0][i]); bx = fmaxf(bx, s4[1][i]);
            cmin = fminf(cmin, s4[2][i]); dmax = fmaxf(dmax, s4[3][i]);
        }
        atomicMin(&g_mm[0], __float_as_uint(a));
        atomicMax(&g_mm[1], __float_as_uint(bx));
        atomicMin(&g_mm[2], __float_as_uint(cmin));
        atomicMax(&g_mm[3], __float_as_uint(dmax));
    }
}

// GME: mean |norm(gm_p) - norm(gm_t)|  (float4 vectorized)
__global__ __launch_bounds__(256) void gme_kernel() {
    const float4* __restrict__ gm = reinterpret_cast<const float4*>(g_gm);
    float minp = __uint_as_float(g_mm[0]), maxp = __uint_as_float(g_mm[1]);
    float mint = __uint_as_float(g_mm[2]), maxt = __uint_as_float(g_mm[3]);
    float ip = 1.f / (maxp - minp + 1e-6f);
    float it = 1.f / (maxt - mint + 1e-6f);
    const int NV4 = NVOX / 4;
    float acc = 0.f;
    for (int i = blockIdx.x*blockDim.x + threadIdx.x; i < NV4;
         i += gridDim.x*blockDim.x) {
        float4 a = gm[i];
        float4 bq = gm[NV4 + i];
        acc += fabsf((a.x - minp)*ip - (bq.x - mint)*it);
        acc += fabsf((a.y - minp)*ip - (bq.y - mint)*it);
        acc += fabsf((a.z - minp)*ip - (bq.z - mint)*it);
        acc += fabsf((a.w - minp)*ip - (bq.w - mint)*it);
    }
    block_add(acc, 2);
}

__global__ void finalize_kernel(float* out, int out_size) {
    if (threadIdx.x == 0) {
        double s0 = 0.0, s1 = 0.0, s2 = 0.0;
        for (int i = 0; i < 64; i++) { s0 += g_part[0][i]; s1 += g_part[1][i]; s2 += g_part[2][i]; }
        const double inv = 1.0 / (double)NVOX;
        double mse  = s0 * inv;
        double ssim = 1.0 - s1 * inv;
        double gme  = 1e-6 + s2 * inv;
        double total = mse + ssim + 0.7 * gme;
        if (out_size > 0) out[0] = (float)total;
        if (out_size > 1) out[1] = (float)mse;
        if (out_size > 2) out[2] = (float)ssim;
        if (out_size > 3) out[3] = (float)gme;
    }
}

// ---------------- launch ----------------
extern "C" void kernel_launch(void* const* d_in, const int* in_sizes, int n_in,
                              void* d_out, int out_size) {
    const float* pred = (const float*)d_in[0];
    const float* targ = (const float*)d_in[1];
    float* out = (float*)d_out;

    init_kernel<<<1, 64>>>();
    fused_wh<<<dim3(BB*DD, HCH), 128>>>(pred, targ);
    pass_d_ssim<<<dim3(HH, BB, DCH), WW>>>();
    sobel_kernel<<<dim3(WW/32, HH/8, BB*16), dim3(32, 8)>>>(pred, targ);
    gme_kernel<<<1024, 256>>>();
    finalize_kernel<<<1, 32>>>(out, out_size);
}

// round 4
// speedup vs baseline: 1.4646x; 1.0813x over previous
#include <cuda_runtime.h>
#include <math.h>

// Problem constants
#define BB 2
#define DD 128
#define HH 128
#define WW 128
#define NVOX (BB*DD*HH*WW)          // 4194304
#define PLANE (HH*WW)               // 16384

// ---------------- static device scratch (no runtime allocation) ----------------
__device__ float g_buf2[5u*NVOX];   // W+H filtered, 5 channels
__device__ float g_gm[2u*NVOX];     // gradient magnitude: pred, target
__device__ double g_part[3][64];    // partial sums: mse, ssim, gme
__device__ unsigned g_mm[4];        // minp, maxp, mint, maxt (float bits, all >0)

// ---------------- helpers ----------------
__device__ __forceinline__ int refl(int x) {      // jnp 'reflect' (no edge repeat)
    return x < 0 ? -x : (x > 127 ? 254 - x : x);
}

__device__ __forceinline__ void load_gauss(float* G) {
    if (threadIdx.x == 0 && threadIdx.y == 0) {
        float tmp[11]; float s = 0.f;
        #pragma unroll
        for (int i = 0; i < 11; i++) {
            float o = (float)(i - 5);
            tmp[i] = expf(-(o*o) / 4.5f);   // 2*1.5^2 = 4.5
            s += tmp[i];
        }
        #pragma unroll
        for (int i = 0; i < 11; i++) G[i] = tmp[i] / s;
    }
}

// Block-wide sum -> double partial slot (1D blocks, size multiple of 32, <=1024)
__device__ __forceinline__ void block_add(float v, int slot) {
    #pragma unroll
    for (int o = 16; o > 0; o >>= 1) v += __shfl_down_sync(0xffffffffu, v, o);
    __shared__ float red[32];
    int lane = threadIdx.x & 31, wid = threadIdx.x >> 5;
    if (lane == 0) red[wid] = v;
    __syncthreads();
    int nw = (blockDim.x + 31) >> 5;
    if (wid == 0) {
        float x = (lane < nw) ? red[lane] : 0.f;
        #pragma unroll
        for (int o = 16; o > 0; o >>= 1) x += __shfl_down_sync(0xffffffffu, x, o);
        if (lane == 0) atomicAdd(&g_part[slot][blockIdx.x & 63], (double)x);
    }
}

// ---------------- kernels ----------------
__global__ void init_kernel() {
    int t = threadIdx.x;
    if (t < 64) { g_part[0][t] = 0.0; g_part[1][t] = 0.0; g_part[2][t] = 0.0; }
    if (t == 0) {
        g_mm[0] = 0x7F800000u; g_mm[1] = 0u;
        g_mm[2] = 0x7F800000u; g_mm[3] = 0u;
    }
}

// Fused W+H Gaussian of {p, t, p^2, t^2, p*t} + MSE partials.
// grid: (BB*DD, 4 h-chunks), block: 128 (w). Ring buffer along H in registers,
// W-conv via double-buffered smem rows; next row's global loads PREFETCHED one
// iteration ahead so the per-row barrier never waits on DRAM latency.
#define HCH 4
#define HROWS (HH/HCH)   // 32
__global__ __launch_bounds__(128) void fused_wh(const float* __restrict__ p,
                                                const float* __restrict__ t) {
    __shared__ float G[11];
    __shared__ float q[2][5][WW];
    load_gauss(G);
    int bd = blockIdx.x;
    int h0 = blockIdx.y * HROWS;
    int w  = threadIdx.x;
    size_t sbase = (size_t)bd * PLANE;

    float win[5][11];
    float msea = 0.f;

    // pending row state (prefetched)
    int  rcur = h0 - 5;
    bool okc  = (rcur >= 0);
    float pv = 0.f, tv = 0.f;
    if (okc) { pv = p[sbase + (size_t)rcur*WW + w]; tv = t[sbase + (size_t)rcur*WW + w]; }
    int par = 0;

    // STEP: stage pending row -> q[par], prefetch next row, sync, W-conv -> DEST.
    // One sync per row; double-buffered q (read of q[a] and next write of q[a]
    // are separated by two barriers -> race-free).
    #define STEP(D0,D1,D2,D3,D4)                                                        \
    {                                                                                   \
        if (okc) {                                                                      \
            q[par][0][w] = pv; q[par][1][w] = tv;                                       \
            q[par][2][w] = pv*pv; q[par][3][w] = tv*tv; q[par][4][w] = pv*tv;           \
            if (rcur >= h0 && rcur < h0 + HROWS) { float dv = pv - tv; msea += dv*dv; } \
        }                                                                               \
        int rn = rcur + 1; bool okn = (rn >= 0 && rn < HH);                             \
        float pn = 0.f, tn = 0.f;                                                       \
        if (okn) { pn = p[sbase + (size_t)rn*WW + w]; tn = t[sbase + (size_t)rn*WW + w]; } \
        __syncthreads();                                                                \
        float a0=0.f,a1=0.f,a2=0.f,a3=0.f,a4=0.f;                                       \
        if (okc) {                                                                      \
            _Pragma("unroll")                                                           \
            for (int k = 0; k < 11; k++) {                                              \
                int ww = w + k - 5;                                                     \
                if (ww >= 0 && ww < WW) {                                               \
                    float g = G[k];                                                     \
                    a0 += g * q[par][0][ww];                                            \
                    a1 += g * q[par][1][ww];                                            \
                    a2 += g * q[par][2][ww];                                            \
                    a3 += g * q[par][3][ww];                                            \
                    a4 += g * q[par][4][ww];                                            \
                }                                                                       \
            }                                                                           \
        }                                                                               \
        D0=a0; D1=a1; D2=a2; D3=a3; D4=a4;                                              \
        pv = pn; tv = tn; okc = okn; rcur = rn; par ^= 1;                               \
    }

    #pragma unroll
    for (int j = 0; j < 11; j++) {
        STEP(win[0][j], win[1][j], win[2][j], win[3][j], win[4][j]);
    }

    for (int h = h0; h < h0 + HROWS; h++) {
        #pragma unroll
        for (int c = 0; c < 5; c++) {
            float acc = 0.f;
            #pragma unroll
            for (int j = 0; j < 11; j++) acc += G[j] * win[c][j];
            g_buf2[(size_t)c*NVOX + sbase + (size_t)h*WW + w] = acc;
        }
        #pragma unroll
        for (int j = 0; j < 10; j++) {
            win[0][j]=win[0][j+1]; win[1][j]=win[1][j+1]; win[2][j]=win[2][j+1];
            win[3][j]=win[3][j+1]; win[4][j]=win[4][j+1];
        }
        STEP(win[0][10], win[1][10], win[2][10], win[3][10], win[4][10]);
    }
    #undef STEP

    block_add(msea, 0);
}

// Gaussian along D of all 5 channels + fused SSIM map + reduction.
// grid: (HH, BB, DCH d-chunks), block: WW
#define DCH 8
#define DROWS (DD/DCH)  // 16
__global__ __launch_bounds__(WW) void pass_d_ssim() {
    __shared__ float G[11];
    load_gauss(G); __syncthreads();
    int h = blockIdx.x, b = blockIdx.y, cz = blockIdx.z;
    int w = threadIdx.x;
    int d0 = cz * DROWS;
    size_t base0 = ((size_t)b*DD*HH + (size_t)h)*WW + w;
    const float* __restrict__ src = g_buf2;

    float win[5][11];
    #pragma unroll
    for (int c = 0; c < 5; c++)
        #pragma unroll
        for (int j = 0; j < 11; j++) {
            int d = d0 + j - 5;
            win[c][j] = (d >= 0 && d < DD)
                ? src[(size_t)c*NVOX + base0 + (size_t)d*PLANE] : 0.f;
        }

    float ssum = 0.f;
    for (int d = d0; d < d0 + DROWS; d++) {
        float f[5];
        #pragma unroll
        for (int c = 0; c < 5; c++) {
            float a = 0.f;
            #pragma unroll
            for (int j = 0; j < 11; j++) a += G[j] * win[c][j];
            f[c] = a;
        }
        float mu_p = f[0], mu_t = f[1];
        float mp2 = mu_p*mu_p, mt2 = mu_t*mu_t, mpt = mu_p*mu_t;
        float sp = f[2] - mp2, st = f[3] - mt2, spt = f[4] - mpt;
        float num = (2.f*mpt + 1e-4f) * (2.f*spt + 9e-4f);
        float den = (mp2 + mt2 + 1e-4f) * (sp + st + 9e-4f);
        ssum += num / den;

        int nd = d + 6;
        #pragma unroll
        for (int c = 0; c < 5; c++) {
            #pragma unroll
            for (int j = 0; j < 10; j++) win[c][j] = win[c][j+1];
            win[c][10] = (nd < DD)
                ? src[(size_t)c*NVOX + base0 + (size_t)nd*PLANE] : 0.f;
        }
    }
    block_add(ssum, 1);
}

// Sobel gradient magnitude. ALL 10 d-planes preloaded into smem with a single
// barrier, then barrier-free compute. Two sequential per-volume passes keep the
// live sliding partials at P[3][7] (21 regs).
//   Sx=s(s)(c)  Sy=s(c)(s)  Sz=c(s)(s)
//   Sd11=B1-B2, Sd12=B1+B2; Sd21=B3-B4, Sd22=B3+B4; Sd31=B5-B6, Sd32=B5+B6
// grid: (WW/32, HH/8, BB*16), block: (32,8). Each block: 8 output planes.
__global__ __launch_bounds__(256) void sobel_kernel(const float* __restrict__ pred,
                                                    const float* __restrict__ targ) {
    __shared__ float tile[10][2][10][36];   // [plane][vol][row][col]
    int tx = threadIdx.x, ty = threadIdx.y;
    int tid = ty * 32 + tx;
    int w0 = blockIdx.x * 32, h0 = blockIdx.y * 8;
    int z = blockIdx.z;
    int b = z >> 4, d0 = (z & 15) * 8;

    // ---- load all 10 planes, one barrier ----
    {
        int gh0 = refl(h0 + ty - 1);                     // row ty
        int gh1 = (ty < 2) ? refl(h0 + ty + 7) : 0;      // row ty+8 (ty<2)
        int gwi = w0 + tx;
        int gl  = refl(w0 - 1), gr = refl(w0 + 32);
        #pragma unroll
        for (int i = 0; i < 10; i++) {
            int gd = refl(d0 - 1 + i);
            size_t pb = ((size_t)b*DD + gd)*PLANE;
            size_t r0 = pb + (size_t)gh0*WW;
            tile[i][0][ty][tx+1] = pred[r0 + gwi];
            tile[i][1][ty][tx+1] = targ[r0 + gwi];
            if (tx == 0)  { tile[i][0][ty][0]  = pred[r0 + gl]; tile[i][1][ty][0]  = targ[r0 + gl]; }
            if (tx == 31) { tile[i][0][ty][33] = pred[r0 + gr]; tile[i][1][ty][33] = targ[r0 + gr]; }
            if (ty < 2) {
                size_t r1 = pb + (size_t)gh1*WW;
                tile[i][0][ty+8][tx+1] = pred[r1 + gwi];
                tile[i][1][ty+8][tx+1] = targ[r1 + gwi];
                if (tx == 0)  { tile[i][0][ty+8][0]  = pred[r1 + gl]; tile[i][1][ty+8][0]  = targ[r1 + gl]; }
                if (tx == 31) { tile[i][0][ty+8][33] = pred[r1 + gr]; tile[i][1][ty+8][33] = targ[r1 + gr]; }
            }
        }
    }
    __syncthreads();

    // ---- compute: 2 sequential volume passes, no barriers ----
    float mnv[2], mxv[2];
    #pragma unroll
    for (int v = 0; v < 2; v++) {
        float P[3][7];
        float mn = 3.4e38f, mx = 0.f;
        #pragma unroll
        for (int i = 0; i < 10; i++) {
            const int ri = i % 3;
            {
                float ws[3], wc[3], wo[3];
                #pragma unroll
                for (int j = 0; j < 3; j++) {
                    float x0 = tile[i][v][ty+j][tx];
                    float x1 = tile[i][v][ty+j][tx+1];
                    float x2 = tile[i][v][ty+j][tx+2];
                    ws[j] = x0 + 2.f*x1 + x2;
                    wc[j] = x2 - x0;
                    wo[j] = x0 + x1 + x2;
                }
                P[ri][0] = wc[0] + 2.f*wc[1] + wc[2];   // s_h of c_w
                P[ri][1] = ws[2] - ws[0];               // c_h of s_w
                P[ri][2] = ws[0] + 2.f*ws[1] + ws[2];   // s_h of s_w
                P[ri][3] = wc[0] + wc[1] + wc[2];       // o_h of c_w
                P[ri][4] = wo[2] - wo[0];               // c_h of o_w
                P[ri][5] = ws[0] + ws[1] + ws[2];       // o_h of s_w
                P[ri][6] = wo[0] + 2.f*wo[1] + wo[2];   // s_h of o_w
            }
            if (i >= 2) {
                const int dm = (i - 2) % 3, dc = (i - 1) % 3, dp = ri;
                int d = d0 + i - 2;
                float gx = P[dm][0] + 2.f*P[dc][0] + P[dp][0];   // Sx
                float gy = P[dm][1] + 2.f*P[dc][1] + P[dp][1];   // Sy
                float gz = P[dp][2] - P[dm][2];                  // Sz
                float B1 = P[dm][3] + 2.f*P[dc][3] + P[dp][3];
                float B2 = P[dm][4] + 2.f*P[dc][4] + P[dp][4];
                float B3 = P[dp][5] - P[dm][5];
                float B4 = P[dm][1] + P[dc][1] + P[dp][1];
                float B5 = P[dm][0] + P[dc][0] + P[dp][0];
                float B6 = P[dp][6] - P[dm][6];
                float g3 = B1 - B2, g4 = B1 + B2;
                float g5 = B3 - B4, g6 = B3 + B4;
                float g7 = B5 - B6, g8 = B5 + B6;

                const float e = 1e-6f;
                float acc = 0.f, qv;
                qv = gx + e; acc += qv*qv;  qv = gy + e; acc += qv*qv;
                qv = gz + e; acc += qv*qv;  qv = g3 + e; acc += qv*qv;
                qv = g4 + e; acc += qv*qv;  qv = g5 + e; acc += qv*qv;
                qv = g6 + e; acc += qv*qv;  qv = g7 + e; acc += qv*qv;
                qv = g8 + e; acc += qv*qv;
                float gm = sqrtf(acc + 9e-6f);

                size_t vox = (((size_t)b*DD + d)*HH + (h0 + ty))*WW + (w0 + tx);
                g_gm[(size_t)v*NVOX + vox] = gm;
                mn = fminf(mn, gm); mx = fmaxf(mx, gm);
            }
        }
        mnv[v] = mn; mxv[v] = mx;
    }

    // block min/max reduction (positive floats -> uint ordering)
    float mn0 = mnv[0], mx0 = mxv[0], mn1 = mnv[1], mx1 = mxv[1];
    #pragma unroll
    for (int o = 16; o > 0; o >>= 1) {
        mn0 = fminf(mn0, __shfl_down_sync(0xffffffffu, mn0, o));
        mx0 = fmaxf(mx0, __shfl_down_sync(0xffffffffu, mx0, o));
        mn1 = fminf(mn1, __shfl_down_sync(0xffffffffu, mn1, o));
        mx1 = fmaxf(mx1, __shfl_down_sync(0xffffffffu, mx1, o));
    }
    __shared__ float s4[4][8];
    int lane = tid & 31, wid = tid >> 5;
    if (lane == 0) { s4[0][wid]=mn0; s4[1][wid]=mx0; s4[2][wid]=mn1; s4[3][wid]=mx1; }
    __syncthreads();
    if (tid == 0) {
        float a = s4[0][0], bx = s4[1][0], cmin = s4[2][0], dmax = s4[3][0];
        #pragma unroll
        for (int i = 1; i < 8; i++) {
            a = fminf(a, s4[0][i]); bx = fmaxf(bx, s4[1][i]);
            cmin = fminf(cmin, s4[2][i]); dmax = fmaxf(dmax, s4[3][i]);
        }
        atomicMin(&g_mm[0], __float_as_uint(a));
        atomicMax(&g_mm[1], __float_as_uint(bx));
        atomicMin(&g_mm[2], __float_as_uint(cmin));
        atomicMax(&g_mm[3], __float_as_uint(dmax));
    }
}

// GME: mean |norm(gm_p) - norm(gm_t)|  (float4 vectorized)
__global__ __launch_bounds__(256) void gme_kernel() {
    const float4* __restrict__ gm = reinterpret_cast<const float4*>(g_gm);
    float minp = __uint_as_float(g_mm[0]), maxp = __uint_as_float(g_mm[1]);
    float mint = __uint_as_float(g_mm[2]), maxt = __uint_as_float(g_mm[3]);
    float ip = 1.f / (maxp - minp + 1e-6f);
    float it = 1.f / (maxt - mint + 1e-6f);
    const int NV4 = NVOX / 4;
    float acc = 0.f;
    for (int i = blockIdx.x*blockDim.x + threadIdx.x; i < NV4;
         i += gridDim.x*blockDim.x) {
        float4 a = gm[i];
        float4 bq = gm[NV4 + i];
        acc += fabsf((a.x - minp)*ip - (bq.x - mint)*it);
        acc += fabsf((a.y - minp)*ip - (bq.y - mint)*it);
        acc += fabsf((a.z - minp)*ip - (bq.z - mint)*it);
        acc += fabsf((a.w - minp)*ip - (bq.w - mint)*it);
    }
    block_add(acc, 2);
}

__global__ void finalize_kernel(float* out, int out_size) {
    if (threadIdx.x == 0) {
        double s0 = 0.0, s1 = 0.0, s2 = 0.0;
        for (int i = 0; i < 64; i++) { s0 += g_part[0][i]; s1 += g_part[1][i]; s2 += g_part[2][i]; }
        const double inv = 1.0 / (double)NVOX;
        double mse  = s0 * inv;
        double ssim = 1.0 - s1 * inv;
        double gme  = 1e-6 + s2 * inv;
        double total = mse + ssim + 0.7 * gme;
        if (out_size > 0) out[0] = (float)total;
        if (out_size > 1) out[1] = (float)mse;
        if (out_size > 2) out[2] = (float)ssim;
        if (out_size > 3) out[3] = (float)gme;
    }
}

// ---------------- launch ----------------
extern "C" void kernel_launch(void* const* d_in, const int* in_sizes, int n_in,
                              void* d_out, int out_size) {
    const float* pred = (const float*)d_in[0];
    const float* targ = (const float*)d_in[1];
    float* out = (float*)d_out;

    init_kernel<<<1, 64>>>();
    fused_wh<<<dim3(BB*DD, HCH), 128>>>(pred, targ);
    pass_d_ssim<<<dim3(HH, BB, DCH), WW>>>();
    sobel_kernel<<<dim3(WW/32, HH/8, BB*16), dim3(32, 8)>>>(pred, targ);
    gme_kernel<<<1024, 256>>>();
    finalize_kernel<<<1, 32>>>(out, out_size);
}